// round 1
// baseline (speedup 1.0000x reference)
#include <cuda_runtime.h>
#include <math.h>

// ---------------------------------------------------------------------------
// Problem constants
// ---------------------------------------------------------------------------
#define S_LEN   512
#define BATCH   64
#define D_IN    256
#define HID     512
#define G4      2048        // 4 gates * HID, packed unit-major: col = u*4 + gate
#define NH      4
#define DK      128
#define ROWS    (S_LEN*BATCH)        // 32768
#define DEC_ELEMS (S_LEN*BATCH*HID)  // 16777216

// ---------------------------------------------------------------------------
// Device scratch (static allocations only — no cudaMalloc allowed)
// ---------------------------------------------------------------------------
__device__ float g_Wxp[D_IN*G4];          //   2 MB  packed input-gate weights
__device__ float g_Whp[HID*G4];           //   4 MB  packed recurrent-gate weights
__device__ float g_biasp[G4];
__device__ float g_gx[ROWS*G4];           // 256 MB  x-side gate preacts; reused as attn scores
__device__ float g_lstm[ROWS*HID];        //  64 MB  lstm_out [S,B,HID] flattened
__device__ float g_h[2][BATCH*HID];       //  h double buffer
__device__ float g_c[BATCH*HID];
__device__ float g_PQ[ROWS*HID];          //  64 MB
__device__ float g_PK[ROWS*HID];
__device__ float g_PV[ROWS*HID];

// ---------------------------------------------------------------------------
// Weight repack: gates (f,i,g,o) interleaved per hid-unit, split x-rows/h-rows
// ---------------------------------------------------------------------------
__global__ void pack_weights(const float* __restrict__ Wf, const float* __restrict__ Wi,
                             const float* __restrict__ Wg, const float* __restrict__ Wo,
                             const float* __restrict__ bf, const float* __restrict__ bi,
                             const float* __restrict__ bg, const float* __restrict__ bo)
{
    int idx = blockIdx.x * blockDim.x + threadIdx.x;   // over 768*512
    if (idx < 768*HID) {
        int k = idx / HID, u = idx % HID;
        float vf = Wf[idx], vi = Wi[idx], vg = Wg[idx], vo = Wo[idx];
        float* dst = (k < D_IN) ? (g_Wxp + (long)k*G4) : (g_Whp + (long)(k - D_IN)*G4);
        dst[u*4+0] = vf; dst[u*4+1] = vi; dst[u*4+2] = vg; dst[u*4+3] = vo;
    }
    if (idx < HID) {
        g_biasp[idx*4+0] = bf[idx];
        g_biasp[idx*4+1] = bi[idx];
        g_biasp[idx*4+2] = bg[idx];
        g_biasp[idx*4+3] = bo[idx];
    }
}

__global__ void zero_hc()
{
    int i = blockIdx.x * blockDim.x + threadIdx.x;
    if (i < BATCH*HID) { g_h[0][i] = 0.f; g_c[i] = 0.f; }
}

// ---------------------------------------------------------------------------
// Generic fp32 GEMM: C = alpha*A@B (+bias). A[M,K] lda, B[K,N] ldb, row-major.
// 64x64 block tile, 256 threads, 4x4 register tile, k-tile 16.
// Batched via blockIdx.z, offsets = (z>>2)*s1 + (z&3)*s2.
// Requires: block-covered M,N; K % 16 == 0; lda/ldb/ldc % 4 == 0.
// ---------------------------------------------------------------------------
__global__ __launch_bounds__(256)
void gemm_nn(const float* __restrict__ A, int lda, long as1, long as2,
             const float* __restrict__ B, int ldb, long bs1, long bs2,
             const float* __restrict__ bias,
             float* __restrict__ C, int ldc, long cs1, long cs2,
             int K, float alpha)
{
    int z = blockIdx.z;
    A += (long)(z >> 2) * as1 + (long)(z & 3) * as2;
    B += (long)(z >> 2) * bs1 + (long)(z & 3) * bs2;
    C += (long)(z >> 2) * cs1 + (long)(z & 3) * cs2;
    int m0 = blockIdx.y * 64, n0 = blockIdx.x * 64;

    __shared__ float As[16][68];
    __shared__ float Bs[16][68];
    int tid = threadIdx.x;
    int ty = tid >> 4, tx = tid & 15;
    float acc[4][4] = {};

    for (int k0 = 0; k0 < K; k0 += 16) {
        {
            int r = tid >> 2, c4 = tid & 3;
            float4 a = *(const float4*)(A + (long)(m0 + r) * lda + k0 + c4 * 4);
            As[c4*4+0][r] = a.x; As[c4*4+1][r] = a.y;
            As[c4*4+2][r] = a.z; As[c4*4+3][r] = a.w;
            int kk = tid >> 4, cc4 = tid & 15;
            float4 b = *(const float4*)(B + (long)(k0 + kk) * ldb + n0 + cc4 * 4);
            *(float4*)(&Bs[kk][cc4*4]) = b;
        }
        __syncthreads();
        #pragma unroll
        for (int kk = 0; kk < 16; kk++) {
            float4 av = *(const float4*)(&As[kk][ty*4]);
            float4 bv = *(const float4*)(&Bs[kk][tx*4]);
            float a_[4] = {av.x, av.y, av.z, av.w};
            float b_[4] = {bv.x, bv.y, bv.z, bv.w};
            #pragma unroll
            for (int i = 0; i < 4; i++)
                #pragma unroll
                for (int j = 0; j < 4; j++)
                    acc[i][j] += a_[i] * b_[j];
        }
        __syncthreads();
    }
    #pragma unroll
    for (int i = 0; i < 4; i++) {
        long m = m0 + ty*4 + i;
        #pragma unroll
        for (int j = 0; j < 4; j++) {
            int n = n0 + tx*4 + j;
            float v = alpha * acc[i][j];
            if (bias) v += bias[n];
            C[m * ldc + n] = v;
        }
    }
}

// C = alpha * A @ B^T   where B is [N,K] row-major (for Q@K^T)
__global__ __launch_bounds__(256)
void gemm_nt(const float* __restrict__ A, int lda, long as1, long as2,
             const float* __restrict__ B, int ldb, long bs1, long bs2,
             float* __restrict__ C, int ldc, long cs1, long cs2,
             int K, float alpha)
{
    int z = blockIdx.z;
    A += (long)(z >> 2) * as1 + (long)(z & 3) * as2;
    B += (long)(z >> 2) * bs1 + (long)(z & 3) * bs2;
    C += (long)(z >> 2) * cs1 + (long)(z & 3) * cs2;
    int m0 = blockIdx.y * 64, n0 = blockIdx.x * 64;

    __shared__ float As[16][68];
    __shared__ float Bs[16][68];
    int tid = threadIdx.x;
    int ty = tid >> 4, tx = tid & 15;
    float acc[4][4] = {};

    for (int k0 = 0; k0 < K; k0 += 16) {
        {
            int r = tid >> 2, c4 = tid & 3;
            float4 a = *(const float4*)(A + (long)(m0 + r) * lda + k0 + c4 * 4);
            As[c4*4+0][r] = a.x; As[c4*4+1][r] = a.y;
            As[c4*4+2][r] = a.z; As[c4*4+3][r] = a.w;
            float4 b = *(const float4*)(B + (long)(n0 + r) * ldb + k0 + c4 * 4);
            Bs[c4*4+0][r] = b.x; Bs[c4*4+1][r] = b.y;
            Bs[c4*4+2][r] = b.z; Bs[c4*4+3][r] = b.w;
        }
        __syncthreads();
        #pragma unroll
        for (int kk = 0; kk < 16; kk++) {
            float4 av = *(const float4*)(&As[kk][ty*4]);
            float4 bv = *(const float4*)(&Bs[kk][tx*4]);
            float a_[4] = {av.x, av.y, av.z, av.w};
            float b_[4] = {bv.x, bv.y, bv.z, bv.w};
            #pragma unroll
            for (int i = 0; i < 4; i++)
                #pragma unroll
                for (int j = 0; j < 4; j++)
                    acc[i][j] += a_[i] * b_[j];
        }
        __syncthreads();
    }
    #pragma unroll
    for (int i = 0; i < 4; i++) {
        long m = m0 + ty*4 + i;
        #pragma unroll
        for (int j = 0; j < 4; j++)
            C[m * ldc + n0 + tx*4 + j] = alpha * acc[i][j];
    }
}

// ---------------------------------------------------------------------------
// One LSTM timestep. Grid = 128 blocks x 256 threads.
// Block j owns hid-units [j*4, j*4+4) x 4 gates (packed cols [j*16, j*16+16)).
// ---------------------------------------------------------------------------
__global__ __launch_bounds__(256)
void lstm_step(const float* __restrict__ hprev,
               const float* __restrict__ gx_t,
               float* __restrict__ cbuf,
               float* __restrict__ hnext,
               float* __restrict__ out_t)
{
    __shared__ float hs[64][68];
    __shared__ float ws[64][16];
    int tid = threadIdx.x;
    int c0 = blockIdx.x * 16;
    int b = tid >> 2, cq = tid & 3;
    float acc0 = 0.f, acc1 = 0.f, acc2 = 0.f, acc3 = 0.f;

    for (int k0 = 0; k0 < HID; k0 += 64) {
        #pragma unroll
        for (int i = 0; i < 4; i++) {
            int l = tid + i * 256;
            int r = l >> 4, c4 = l & 15;
            float4 v = *(const float4*)(hprev + r * HID + k0 + c4 * 4);
            *(float4*)(&hs[r][c4*4]) = v;
        }
        {
            int kk = tid >> 2, c4v = tid & 3;
            float4 w = *(const float4*)(g_Whp + (long)(k0 + kk) * G4 + c0 + c4v * 4);
            *(float4*)(&ws[kk][c4v*4]) = w;
        }
        __syncthreads();
        #pragma unroll
        for (int kk = 0; kk < 64; kk++) {
            float hv = hs[b][kk];
            float4 wv = *(const float4*)(&ws[kk][cq*4]);
            acc0 += hv * wv.x; acc1 += hv * wv.y;
            acc2 += hv * wv.z; acc3 += hv * wv.w;
        }
        __syncthreads();
    }

    int u = (c0 >> 2) + cq;
    const float* gxr = gx_t + b * G4 + c0 + cq * 4;
    float pf = acc0 + gxr[0];
    float pi = acc1 + gxr[1];
    float pg = acc2 + gxr[2];
    float po = acc3 + gxr[3];
    float f  = 1.f / (1.f + expf(-pf));
    float ii = 1.f / (1.f + expf(-pi));
    float gg = tanhf(pg);
    float o  = 1.f / (1.f + expf(-po));
    float cn = f * cbuf[b * HID + u] + ii * gg;
    cbuf[b * HID + u] = cn;
    float hn = o * tanhf(cn);
    hnext[b * HID + u] = hn;
    out_t[b * HID + u] = hn;
}

// ---------------------------------------------------------------------------
// Row softmax over 512-wide rows. One block (128 threads) per row.
// ---------------------------------------------------------------------------
__global__ __launch_bounds__(128)
void softmax512(float* __restrict__ s)
{
    float* row = s + (size_t)blockIdx.x * 512;
    int tid = threadIdx.x;
    float v0 = row[tid], v1 = row[tid+128], v2 = row[tid+256], v3 = row[tid+384];
    float mx = fmaxf(fmaxf(v0, v1), fmaxf(v2, v3));
    __shared__ float sm[4];
    __shared__ float ss[4];
    #pragma unroll
    for (int off = 16; off > 0; off >>= 1)
        mx = fmaxf(mx, __shfl_xor_sync(0xFFFFFFFFu, mx, off));
    if ((tid & 31) == 0) sm[tid >> 5] = mx;
    __syncthreads();
    mx = fmaxf(fmaxf(sm[0], sm[1]), fmaxf(sm[2], sm[3]));
    v0 = expf(v0 - mx); v1 = expf(v1 - mx); v2 = expf(v2 - mx); v3 = expf(v3 - mx);
    float sum = v0 + v1 + v2 + v3;
    #pragma unroll
    for (int off = 16; off > 0; off >>= 1)
        sum += __shfl_xor_sync(0xFFFFFFFFu, sum, off);
    if ((tid & 31) == 0) ss[tid >> 5] = sum;
    __syncthreads();
    sum = ss[0] + ss[1] + ss[2] + ss[3];
    float inv = 1.f / sum;
    row[tid] = v0*inv; row[tid+128] = v1*inv; row[tid+256] = v2*inv; row[tid+384] = v3*inv;
}

__global__ void copy_hc(const float* __restrict__ h, const float* __restrict__ c,
                        float* __restrict__ out)
{
    int i = blockIdx.x * blockDim.x + threadIdx.x;
    if (i < BATCH*HID) {
        out[DEC_ELEMS + i] = h[i];
        out[DEC_ELEMS + BATCH*HID + i] = c[i];
    }
}

// ---------------------------------------------------------------------------
// Host orchestration (graph-capturable: launches only)
// ---------------------------------------------------------------------------
extern "C" void kernel_launch(void* const* d_in, const int* in_sizes, int n_in,
                              void* d_out, int out_size)
{
    const float* x  = (const float*)d_in[0];
    const float* Wf = (const float*)d_in[1];
    const float* bf = (const float*)d_in[2];
    const float* Wi = (const float*)d_in[3];
    const float* bi = (const float*)d_in[4];
    const float* Wg = (const float*)d_in[5];
    const float* bg = (const float*)d_in[6];
    const float* Wo = (const float*)d_in[7];
    const float* bo = (const float*)d_in[8];
    const float* Wq = (const float*)d_in[9];
    const float* bq = (const float*)d_in[10];
    const float* Wk = (const float*)d_in[11];
    const float* bk = (const float*)d_in[12];
    const float* Wv = (const float*)d_in[13];
    const float* bv = (const float*)d_in[14];
    float* out = (float*)d_out;

    float *Wxp, *biasp, *gx, *lstm, *hbase, *c, *PQ, *PK, *PV;
    cudaGetSymbolAddress((void**)&Wxp,   g_Wxp);
    cudaGetSymbolAddress((void**)&biasp, g_biasp);
    cudaGetSymbolAddress((void**)&gx,    g_gx);
    cudaGetSymbolAddress((void**)&lstm,  g_lstm);
    cudaGetSymbolAddress((void**)&hbase, g_h);
    cudaGetSymbolAddress((void**)&c,     g_c);
    cudaGetSymbolAddress((void**)&PQ,    g_PQ);
    cudaGetSymbolAddress((void**)&PK,    g_PK);
    cudaGetSymbolAddress((void**)&PV,    g_PV);
    float* h0 = hbase;
    float* h1 = hbase + BATCH*HID;

    // 1. repack weights + zero state
    pack_weights<<<(768*HID + 255)/256, 256>>>(Wf, Wi, Wg, Wo, bf, bi, bg, bo);
    zero_hc<<<(BATCH*HID + 255)/256, 256>>>();

    // 2. x-side gate preacts: gx = x @ Wxp + biasp   [32768,256]@[256,2048]
    gemm_nn<<<dim3(G4/64, ROWS/64, 1), 256>>>(
        x, D_IN, 0, 0, Wxp, G4, 0, 0, biasp, gx, G4, 0, 0, D_IN, 1.0f);

    // 3. recurrence: 512 sequential step kernels (double-buffered h)
    for (int t = 0; t < S_LEN; t++) {
        const float* hp = (t & 1) ? h1 : h0;
        float*       hn = (t & 1) ? h0 : h1;
        lstm_step<<<128, 256>>>(hp, gx + (long)t * BATCH * G4, c, hn,
                                lstm + (long)t * BATCH * HID);
    }

    // 4. Q/K/V projections: [32768,512]@[512,512]+b
    gemm_nn<<<dim3(HID/64, ROWS/64, 1), 256>>>(
        lstm, HID, 0, 0, Wq, HID, 0, 0, bq, PQ, HID, 0, 0, HID, 1.0f);
    gemm_nn<<<dim3(HID/64, ROWS/64, 1), 256>>>(
        lstm, HID, 0, 0, Wk, HID, 0, 0, bk, PK, HID, 0, 0, HID, 1.0f);
    gemm_nn<<<dim3(HID/64, ROWS/64, 1), 256>>>(
        lstm, HID, 0, 0, Wv, HID, 0, 0, bv, PV, HID, 0, 0, HID, 1.0f);

    // 5. scores = (Q @ K^T)/sqrt(dk), z = b'*4 + h
    //    q[b',h,s,d] = PQ[(b'*512 + s)*512 + h*128 + d]
    const long pbS = (long)S_LEN * HID;          // per-b' stride in PQ/PK/PV
    const long phS = DK;                         // per-h stride
    const long scB = 4L * S_LEN * S_LEN;         // scores per-b' stride
    const long scH = (long)S_LEN * S_LEN;        // scores per-h stride
    float scale = 1.0f / sqrtf((float)DK);
    gemm_nt<<<dim3(S_LEN/64, S_LEN/64, BATCH*NH), 256>>>(
        PQ, HID, pbS, phS,
        PK, HID, pbS, phS,
        gx /* reused as scores */, S_LEN, scB, scH, DK, scale);

    // 6. softmax over last axis
    softmax512<<<BATCH*NH*S_LEN, 128>>>(gx);

    // 7. out = attn @ V, written directly in decoded layout:
    //    d_out[(s*64 + b')*512 + h*128 + d]  -> ldc = 32768,
    //    per-z C offset = b'*512 + h*128
    gemm_nn<<<dim3(DK/64, S_LEN/64, BATCH*NH), 256>>>(
        gx, S_LEN, scB, scH,
        PV, HID, pbS, phS,
        (const float*)0,
        out, BATCH*HID /* 32768 */, (long)HID, (long)DK,
        S_LEN, 1.0f);

    // 8. final hidden/cell state (after step 511 the live h buffer is h0)
    copy_hc<<<(BATCH*HID + 255)/256, 256>>>(h0, c, out);
}

// round 2
// speedup vs baseline: 1.2167x; 1.2167x over previous
#include <cuda_runtime.h>
#include <math.h>

// ---------------------------------------------------------------------------
// Problem constants
// ---------------------------------------------------------------------------
#define S_LEN   512
#define BATCH   64
#define D_IN    256
#define HID     512
#define G4      2048        // 4 gates * HID, packed unit-major: col = u*4 + gate
#define NH      4
#define DK      128
#define ROWS    (S_LEN*BATCH)        // 32768
#define DEC_ELEMS (S_LEN*BATCH*HID)  // 16777216
#define NB      128                  // persistent LSTM blocks
#define HPAD    516                  // padded h row (bank-conflict-free)

// ---------------------------------------------------------------------------
// Device scratch (static allocations only — no cudaMalloc allowed)
// ---------------------------------------------------------------------------
__device__ float g_Wxp[D_IN*G4];          //   2 MB  packed input-gate weights
__device__ float g_Whp[HID*G4];           //   4 MB  packed recurrent-gate weights
__device__ float g_biasp[G4];
__device__ float g_gx[ROWS*G4];           // 256 MB  x-side gate preacts; reused as attn scores
__device__ float g_lstm[ROWS*HID];        //  64 MB  lstm_out [S,B,HID] flattened
__device__ float g_h[2][BATCH*HID];       //  h double buffer
__device__ float g_c[BATCH*HID];
__device__ float g_PQ[ROWS*HID];          //  64 MB
__device__ float g_PK[ROWS*HID];
__device__ float g_PV[ROWS*HID];
__device__ unsigned g_cnt;                //  grid barrier counter

// ---------------------------------------------------------------------------
// Weight repack: gates (f,i,g,o) interleaved per hid-unit, split x-rows/h-rows
// ---------------------------------------------------------------------------
__global__ void pack_weights(const float* __restrict__ Wf, const float* __restrict__ Wi,
                             const float* __restrict__ Wg, const float* __restrict__ Wo,
                             const float* __restrict__ bf, const float* __restrict__ bi,
                             const float* __restrict__ bg, const float* __restrict__ bo)
{
    int idx = blockIdx.x * blockDim.x + threadIdx.x;   // over 768*512
    if (idx < 768*HID) {
        int k = idx / HID, u = idx % HID;
        float vf = Wf[idx], vi = Wi[idx], vg = Wg[idx], vo = Wo[idx];
        float* dst = (k < D_IN) ? (g_Wxp + (long)k*G4) : (g_Whp + (long)(k - D_IN)*G4);
        dst[u*4+0] = vf; dst[u*4+1] = vi; dst[u*4+2] = vg; dst[u*4+3] = vo;
    }
    if (idx < HID) {
        g_biasp[idx*4+0] = bf[idx];
        g_biasp[idx*4+1] = bi[idx];
        g_biasp[idx*4+2] = bg[idx];
        g_biasp[idx*4+3] = bo[idx];
    }
}

__global__ void zero_state()
{
    int i = blockIdx.x * blockDim.x + threadIdx.x;
    if (i < BATCH*HID) g_h[0][i] = 0.f;
    if (i == 0) g_cnt = 0u;
}

// ---------------------------------------------------------------------------
// Generic fp32 GEMM: C = alpha*A@B (+bias). A[M,K] lda, B[K,N] ldb, row-major.
// 64x64 block tile, 256 threads, 4x4 register tile, k-tile 16.
// Batched via blockIdx.z, offsets = (z>>2)*s1 + (z&3)*s2.
// ---------------------------------------------------------------------------
__global__ __launch_bounds__(256)
void gemm_nn(const float* __restrict__ A, int lda, long as1, long as2,
             const float* __restrict__ B, int ldb, long bs1, long bs2,
             const float* __restrict__ bias,
             float* __restrict__ C, int ldc, long cs1, long cs2,
             int K, float alpha)
{
    int z = blockIdx.z;
    A += (long)(z >> 2) * as1 + (long)(z & 3) * as2;
    B += (long)(z >> 2) * bs1 + (long)(z & 3) * bs2;
    C += (long)(z >> 2) * cs1 + (long)(z & 3) * cs2;
    int m0 = blockIdx.y * 64, n0 = blockIdx.x * 64;

    __shared__ float As[16][68];
    __shared__ float Bs[16][68];
    int tid = threadIdx.x;
    int ty = tid >> 4, tx = tid & 15;
    float acc[4][4] = {};

    for (int k0 = 0; k0 < K; k0 += 16) {
        {
            int r = tid >> 2, c4 = tid & 3;
            float4 a = *(const float4*)(A + (long)(m0 + r) * lda + k0 + c4 * 4);
            As[c4*4+0][r] = a.x; As[c4*4+1][r] = a.y;
            As[c4*4+2][r] = a.z; As[c4*4+3][r] = a.w;
            int kk = tid >> 4, cc4 = tid & 15;
            float4 b = *(const float4*)(B + (long)(k0 + kk) * ldb + n0 + cc4 * 4);
            *(float4*)(&Bs[kk][cc4*4]) = b;
        }
        __syncthreads();
        #pragma unroll
        for (int kk = 0; kk < 16; kk++) {
            float4 av = *(const float4*)(&As[kk][ty*4]);
            float4 bv = *(const float4*)(&Bs[kk][tx*4]);
            float a_[4] = {av.x, av.y, av.z, av.w};
            float b_[4] = {bv.x, bv.y, bv.z, bv.w};
            #pragma unroll
            for (int i = 0; i < 4; i++)
                #pragma unroll
                for (int j = 0; j < 4; j++)
                    acc[i][j] += a_[i] * b_[j];
        }
        __syncthreads();
    }
    #pragma unroll
    for (int i = 0; i < 4; i++) {
        long m = m0 + ty*4 + i;
        #pragma unroll
        for (int j = 0; j < 4; j++) {
            int n = n0 + tx*4 + j;
            float v = alpha * acc[i][j];
            if (bias) v += bias[n];
            C[m * ldc + n] = v;
        }
    }
}

// C = alpha * A @ B^T   where B is [N,K] row-major (for Q@K^T)
__global__ __launch_bounds__(256)
void gemm_nt(const float* __restrict__ A, int lda, long as1, long as2,
             const float* __restrict__ B, int ldb, long bs1, long bs2,
             float* __restrict__ C, int ldc, long cs1, long cs2,
             int K, float alpha)
{
    int z = blockIdx.z;
    A += (long)(z >> 2) * as1 + (long)(z & 3) * as2;
    B += (long)(z >> 2) * bs1 + (long)(z & 3) * bs2;
    C += (long)(z >> 2) * cs1 + (long)(z & 3) * cs2;
    int m0 = blockIdx.y * 64, n0 = blockIdx.x * 64;

    __shared__ float As[16][68];
    __shared__ float Bs[16][68];
    int tid = threadIdx.x;
    int ty = tid >> 4, tx = tid & 15;
    float acc[4][4] = {};

    for (int k0 = 0; k0 < K; k0 += 16) {
        {
            int r = tid >> 2, c4 = tid & 3;
            float4 a = *(const float4*)(A + (long)(m0 + r) * lda + k0 + c4 * 4);
            As[c4*4+0][r] = a.x; As[c4*4+1][r] = a.y;
            As[c4*4+2][r] = a.z; As[c4*4+3][r] = a.w;
            float4 b = *(const float4*)(B + (long)(n0 + r) * ldb + k0 + c4 * 4);
            Bs[c4*4+0][r] = b.x; Bs[c4*4+1][r] = b.y;
            Bs[c4*4+2][r] = b.z; Bs[c4*4+3][r] = b.w;
        }
        __syncthreads();
        #pragma unroll
        for (int kk = 0; kk < 16; kk++) {
            float4 av = *(const float4*)(&As[kk][ty*4]);
            float4 bv = *(const float4*)(&Bs[kk][tx*4]);
            float a_[4] = {av.x, av.y, av.z, av.w};
            float b_[4] = {bv.x, bv.y, bv.z, bv.w};
            #pragma unroll
            for (int i = 0; i < 4; i++)
                #pragma unroll
                for (int j = 0; j < 4; j++)
                    acc[i][j] += a_[i] * b_[j];
        }
        __syncthreads();
    }
    #pragma unroll
    for (int i = 0; i < 4; i++) {
        long m = m0 + ty*4 + i;
        #pragma unroll
        for (int j = 0; j < 4; j++)
            C[m * ldc + n0 + tx*4 + j] = alpha * acc[i][j];
    }
}

// ---------------------------------------------------------------------------
// Persistent LSTM recurrence. Grid = NB=128 blocks (all resident), 256 thr.
// Block bid owns hid-units [bid*4, bid*4+4) (packed cols [bid*16,bid*16+16)).
// Weights slice resident in SMEM for all 512 steps; c in registers;
// h double-buffered in global, separated by a device grid barrier.
// Thread (b = tid>>2, cq = tid&3) produces gates f,i,g,o of unit bid*4+cq
// for batch row b.
// ---------------------------------------------------------------------------
__global__ __launch_bounds__(256)
void lstm_persistent(const float* __restrict__ gx)
{
    extern __shared__ float sm[];
    float* ws = sm;                 // [512][16]  weight slice (32 KB)
    float* hs = sm + HID*16;        // [64][HPAD] staged h     (132 KB)

    int tid = threadIdx.x, bid = blockIdx.x;
    int c0 = bid * 16;

    // preload weight slice: 2048 float4
    #pragma unroll
    for (int i = 0; i < 8; i++) {
        int idx = tid + i*256;
        int k = idx >> 2, j4 = idx & 3;
        float4 w = *(const float4*)(g_Whp + (long)k*G4 + c0 + j4*4);
        *(float4*)(ws + k*16 + j4*4) = w;
    }

    int b = tid >> 2, cq = tid & 3;
    int u = bid*4 + cq;
    float creg = 0.f;
    float* h0 = g_h[0];
    float* h1 = g_h[1];

    __syncthreads();

    for (int t = 0; t < S_LEN; t++) {
        // wait for all blocks to finish step t-1
        if (t) {
            if (tid == 0) {
                unsigned target = (unsigned)t * NB;
                while (*(volatile unsigned*)&g_cnt < target) { }
                __threadfence();
            }
            __syncthreads();
        }

        // stage h_prev (L2-only loads: other SMs wrote it) + this step's gx
        const float* hr = (t & 1) ? h1 : h0;
        #pragma unroll 8
        for (int i = 0; i < 32; i++) {
            int idx = tid + i*256;               // float4 index, 8192 total
            int r = idx >> 7, cc = idx & 127;
            float4 v = __ldcg((const float4*)hr + idx);
            *(float4*)(hs + r*HPAD + cc*4) = v;
        }
        float4 gv = *(const float4*)(gx + ((long)t*BATCH + b)*G4 + c0 + cq*4);
        __syncthreads();

        // acc[g] = sum_k h[b][k] * w[k][cq*4+g]
        float ax = 0.f, ay = 0.f, az = 0.f, aw = 0.f;
        const float*  hrow = hs + b*HPAD;
        const float4* wq   = (const float4*)ws + cq;
        #pragma unroll 8
        for (int k = 0; k < HID; k += 4) {
            float4 hv = *(const float4*)(hrow + k);
            float4 w0 = wq[(k+0)*4];
            float4 w1 = wq[(k+1)*4];
            float4 w2 = wq[(k+2)*4];
            float4 w3 = wq[(k+3)*4];
            ax = fmaf(hv.x, w0.x, ax); ay = fmaf(hv.x, w0.y, ay);
            az = fmaf(hv.x, w0.z, az); aw = fmaf(hv.x, w0.w, aw);
            ax = fmaf(hv.y, w1.x, ax); ay = fmaf(hv.y, w1.y, ay);
            az = fmaf(hv.y, w1.z, az); aw = fmaf(hv.y, w1.w, aw);
            ax = fmaf(hv.z, w2.x, ax); ay = fmaf(hv.z, w2.y, ay);
            az = fmaf(hv.z, w2.z, az); aw = fmaf(hv.z, w2.w, aw);
            ax = fmaf(hv.w, w3.x, ax); ay = fmaf(hv.w, w3.y, ay);
            az = fmaf(hv.w, w3.z, az); aw = fmaf(hv.w, w3.w, aw);
        }

        float pf = ax + gv.x;
        float pi = ay + gv.y;
        float pg = az + gv.z;
        float po = aw + gv.w;
        float f  = 1.f / (1.f + expf(-pf));
        float ii = 1.f / (1.f + expf(-pi));
        float gg = tanhf(pg);
        float o  = 1.f / (1.f + expf(-po));
        creg = f * creg + ii * gg;
        float hn = o * tanhf(creg);

        float* hw = (t & 1) ? h0 : h1;
        hw[b*HID + u] = hn;
        g_lstm[((long)t*BATCH + b)*HID + u] = hn;
        if (t == S_LEN-1) g_c[b*HID + u] = creg;

        __threadfence();
        __syncthreads();
        if (tid == 0) atomicAdd(&g_cnt, 1u);
    }
}

// ---------------------------------------------------------------------------
// Row softmax over 512-wide rows. One block (128 threads) per row.
// ---------------------------------------------------------------------------
__global__ __launch_bounds__(128)
void softmax512(float* __restrict__ s)
{
    float* row = s + (size_t)blockIdx.x * 512;
    int tid = threadIdx.x;
    float v0 = row[tid], v1 = row[tid+128], v2 = row[tid+256], v3 = row[tid+384];
    float mx = fmaxf(fmaxf(v0, v1), fmaxf(v2, v3));
    __shared__ float sm[4];
    __shared__ float ss[4];
    #pragma unroll
    for (int off = 16; off > 0; off >>= 1)
        mx = fmaxf(mx, __shfl_xor_sync(0xFFFFFFFFu, mx, off));
    if ((tid & 31) == 0) sm[tid >> 5] = mx;
    __syncthreads();
    mx = fmaxf(fmaxf(sm[0], sm[1]), fmaxf(sm[2], sm[3]));
    v0 = expf(v0 - mx); v1 = expf(v1 - mx); v2 = expf(v2 - mx); v3 = expf(v3 - mx);
    float sum = v0 + v1 + v2 + v3;
    #pragma unroll
    for (int off = 16; off > 0; off >>= 1)
        sum += __shfl_xor_sync(0xFFFFFFFFu, sum, off);
    if ((tid & 31) == 0) ss[tid >> 5] = sum;
    __syncthreads();
    sum = ss[0] + ss[1] + ss[2] + ss[3];
    float inv = 1.f / sum;
    row[tid] = v0*inv; row[tid+128] = v1*inv; row[tid+256] = v2*inv; row[tid+384] = v3*inv;
}

__global__ void copy_hc(const float* __restrict__ h, const float* __restrict__ c,
                        float* __restrict__ out)
{
    int i = blockIdx.x * blockDim.x + threadIdx.x;
    if (i < BATCH*HID) {
        out[DEC_ELEMS + i] = h[i];
        out[DEC_ELEMS + BATCH*HID + i] = c[i];
    }
}

// ---------------------------------------------------------------------------
// Host orchestration (graph-capturable: launches only)
// ---------------------------------------------------------------------------
extern "C" void kernel_launch(void* const* d_in, const int* in_sizes, int n_in,
                              void* d_out, int out_size)
{
    const float* x  = (const float*)d_in[0];
    const float* Wf = (const float*)d_in[1];
    const float* bf = (const float*)d_in[2];
    const float* Wi = (const float*)d_in[3];
    const float* bi = (const float*)d_in[4];
    const float* Wg = (const float*)d_in[5];
    const float* bg = (const float*)d_in[6];
    const float* Wo = (const float*)d_in[7];
    const float* bo = (const float*)d_in[8];
    const float* Wq = (const float*)d_in[9];
    const float* bq = (const float*)d_in[10];
    const float* Wk = (const float*)d_in[11];
    const float* bk = (const float*)d_in[12];
    const float* Wv = (const float*)d_in[13];
    const float* bv = (const float*)d_in[14];
    float* out = (float*)d_out;

    float *Wxp, *biasp, *gx, *lstm, *hbase, *c, *PQ, *PK, *PV;
    cudaGetSymbolAddress((void**)&Wxp,   g_Wxp);
    cudaGetSymbolAddress((void**)&biasp, g_biasp);
    cudaGetSymbolAddress((void**)&gx,    g_gx);
    cudaGetSymbolAddress((void**)&lstm,  g_lstm);
    cudaGetSymbolAddress((void**)&hbase, g_h);
    cudaGetSymbolAddress((void**)&c,     g_c);
    cudaGetSymbolAddress((void**)&PQ,    g_PQ);
    cudaGetSymbolAddress((void**)&PK,    g_PK);
    cudaGetSymbolAddress((void**)&PV,    g_PV);
    float* h0 = hbase;

    // persistent kernel needs >48KB dynamic SMEM
    const int SMEM_LSTM = (HID*16 + BATCH*HPAD) * (int)sizeof(float);  // 164,864 B
    static int smem_set = 0;
    if (!smem_set) {
        cudaFuncSetAttribute(lstm_persistent,
                             cudaFuncAttributeMaxDynamicSharedMemorySize, SMEM_LSTM);
        smem_set = 1;
    }

    // 1. repack weights + zero h0/barrier
    pack_weights<<<(768*HID + 255)/256, 256>>>(Wf, Wi, Wg, Wo, bf, bi, bg, bo);
    zero_state<<<(BATCH*HID + 255)/256, 256>>>();

    // 2. x-side gate preacts: gx = x @ Wxp + biasp   [32768,256]@[256,2048]
    gemm_nn<<<dim3(G4/64, ROWS/64, 1), 256>>>(
        x, D_IN, 0, 0, Wxp, G4, 0, 0, biasp, gx, G4, 0, 0, D_IN, 1.0f);

    // 3. recurrence: single persistent kernel, device grid barrier per step
    lstm_persistent<<<NB, 256, SMEM_LSTM>>>(gx);

    // 4. Q/K/V projections: [32768,512]@[512,512]+b
    gemm_nn<<<dim3(HID/64, ROWS/64, 1), 256>>>(
        lstm, HID, 0, 0, Wq, HID, 0, 0, bq, PQ, HID, 0, 0, HID, 1.0f);
    gemm_nn<<<dim3(HID/64, ROWS/64, 1), 256>>>(
        lstm, HID, 0, 0, Wk, HID, 0, 0, bk, PK, HID, 0, 0, HID, 1.0f);
    gemm_nn<<<dim3(HID/64, ROWS/64, 1), 256>>>(
        lstm, HID, 0, 0, Wv, HID, 0, 0, bv, PV, HID, 0, 0, HID, 1.0f);

    // 5. scores = (Q @ K^T)/sqrt(dk), z = b'*4 + h
    const long pbS = (long)S_LEN * HID;
    const long phS = DK;
    const long scB = 4L * S_LEN * S_LEN;
    const long scH = (long)S_LEN * S_LEN;
    float scale = 1.0f / sqrtf((float)DK);
    gemm_nt<<<dim3(S_LEN/64, S_LEN/64, BATCH*NH), 256>>>(
        PQ, HID, pbS, phS,
        PK, HID, pbS, phS,
        gx /* reused as scores */, S_LEN, scB, scH, DK, scale);

    // 6. softmax over last axis
    softmax512<<<BATCH*NH*S_LEN, 128>>>(gx);

    // 7. out = attn @ V, written directly in decoded layout
    gemm_nn<<<dim3(DK/64, S_LEN/64, BATCH*NH), 256>>>(
        gx, S_LEN, scB, scH,
        PV, HID, pbS, phS,
        (const float*)0,
        out, BATCH*HID, (long)HID, (long)DK,
        S_LEN, 1.0f);

    // 8. final hidden/cell state (after step 511 the live h buffer is h0)
    copy_hc<<<(BATCH*HID + 255)/256, 256>>>(h0, c, out);
}